// round 4
// baseline (speedup 1.0000x reference)
#include <cuda_runtime.h>
#include <cstdint>

// Problem constants: x(8,1024,256), adj(8,1024,1024), W(256,256), a(1,4,128)
#define Bb    8
#define Nn    1024
#define Cc    256
#define Hh    4
#define Dd    64
#define Mrows (Bb*Nn)   // 8192 token rows
#define HD    (Hh*Dd)   // 256

// Scratch (static device arrays: no allocation allowed)
__device__ __align__(16) static float g_Wx[Mrows*HD];   // 8.4 MB
__device__ __align__(16) static float g_ei[Mrows*Hh];
__device__ __align__(16) static float g_ej[Mrows*Hh];

// ---------------- packed f32x2 helpers (Blackwell 2x fp32 path) ----------------
__device__ __forceinline__ unsigned long long pk2(float v) {
    unsigned long long r; unsigned u = __float_as_uint(v);
    asm("mov.b64 %0, {%1, %1};" : "=l"(r) : "r"(u));
    return r;
}
__device__ __forceinline__ void fma2(unsigned long long& c, unsigned long long a, unsigned long long b) {
    asm("fma.rn.f32x2 %0, %1, %2, %3;" : "=l"(c) : "l"(a), "l"(b), "l"(c));
}

// ---------------- Kernel A: Wx = x @ W  (M=8192, N=256, K=256) ----------------
#define BM 128
#define BN 64
#define BK 16

__global__ __launch_bounds__(256) void gemm_kernel(const float* __restrict__ x,
                                                   const float* __restrict__ W) {
    __shared__ __align__(16) float As[BK][BM + 2];  // transposed: As[k][m], pad keeps 8B align
    __shared__ __align__(16) float Bs[BK][BN];

    const int t  = threadIdx.x;
    const int bm = blockIdx.x * BM;
    const int bn = blockIdx.y * BN;
    const int tx = t & 15;   // col group: 4 cols each
    const int ty = t >> 4;   // row group: 8 rows each

    unsigned long long acc[4][4];  // [row-pair][col] — each holds 2 fp32 (rows 2rp, 2rp+1)
#pragma unroll
    for (int i = 0; i < 4; i++)
#pragma unroll
        for (int j = 0; j < 4; j++) acc[i][j] = 0ull;

    const int lrow = t >> 1;        // 0..127
    const int lk   = (t & 1) * 8;   // 0 or 8

    for (int k0 = 0; k0 < Cc; k0 += BK) {
        // A tile: 128x16, each thread loads 8 floats, stores transposed
        {
            const float* src = x + (size_t)(bm + lrow) * Cc + k0 + lk;
            float4 v0 = *reinterpret_cast<const float4*>(src);
            float4 v1 = *reinterpret_cast<const float4*>(src + 4);
            As[lk + 0][lrow] = v0.x; As[lk + 1][lrow] = v0.y;
            As[lk + 2][lrow] = v0.z; As[lk + 3][lrow] = v0.w;
            As[lk + 4][lrow] = v1.x; As[lk + 5][lrow] = v1.y;
            As[lk + 6][lrow] = v1.z; As[lk + 7][lrow] = v1.w;
        }
        // B tile: 16x64
        {
            const int kr = t >> 4;
            const int nc = (t & 15) * 4;
            float4 v = *reinterpret_cast<const float4*>(W + (size_t)(k0 + kr) * HD + bn + nc);
            *reinterpret_cast<float4*>(&Bs[kr][nc]) = v;
        }
        __syncthreads();

#pragma unroll
        for (int kk = 0; kk < BK; kk++) {
            const float* ap = &As[kk][ty * 8];
            unsigned long long a0 = *reinterpret_cast<const unsigned long long*>(ap + 0);
            unsigned long long a1 = *reinterpret_cast<const unsigned long long*>(ap + 2);
            unsigned long long a2 = *reinterpret_cast<const unsigned long long*>(ap + 4);
            unsigned long long a3 = *reinterpret_cast<const unsigned long long*>(ap + 6);
            const float* bp = &Bs[kk][tx * 4];
            unsigned long long b0 = pk2(bp[0]);
            unsigned long long b1 = pk2(bp[1]);
            unsigned long long b2 = pk2(bp[2]);
            unsigned long long b3 = pk2(bp[3]);
            fma2(acc[0][0], a0, b0); fma2(acc[0][1], a0, b1); fma2(acc[0][2], a0, b2); fma2(acc[0][3], a0, b3);
            fma2(acc[1][0], a1, b0); fma2(acc[1][1], a1, b1); fma2(acc[1][2], a1, b2); fma2(acc[1][3], a1, b3);
            fma2(acc[2][0], a2, b0); fma2(acc[2][1], a2, b1); fma2(acc[2][2], a2, b2); fma2(acc[2][3], a2, b3);
            fma2(acc[3][0], a3, b0); fma2(acc[3][1], a3, b1); fma2(acc[3][2], a3, b2); fma2(acc[3][3], a3, b3);
        }
        __syncthreads();
    }

#pragma unroll
    for (int rp = 0; rp < 4; rp++) {
        const int r = bm + ty * 8 + rp * 2;
#pragma unroll
        for (int q = 0; q < 4; q++) {
            float2 v = *reinterpret_cast<float2*>(&acc[rp][q]);
            g_Wx[(size_t)r * HD + bn + tx * 4 + q]       = v.x;
            g_Wx[(size_t)(r + 1) * HD + bn + tx * 4 + q] = v.y;
        }
    }
}

// ---------------- Kernel B: e_i / e_j per (token, head) ----------------
// One warp per token row; lane l handles channels [8l, 8l+8) -> head h = l>>3.
__global__ __launch_bounds__(256) void eij_kernel(const float* __restrict__ a) {
    __shared__ float sa[2 * Hh * Dd];  // a[h][0:64]=a_i, a[h][64:128]=a_j
    const int t = threadIdx.x;
    if (t < 128) reinterpret_cast<float4*>(sa)[t] = reinterpret_cast<const float4*>(a)[t];
    __syncthreads();

    const int warp = t >> 5, lane = t & 31;
    const int row  = blockIdx.x * 8 + warp;
    const float* wr = g_Wx + (size_t)row * HD;
    const int c0 = lane * 8;
    const int h  = c0 >> 6;
    const int d0 = c0 & 63;

    float4 wa = *reinterpret_cast<const float4*>(wr + c0);
    float4 wb = *reinterpret_cast<const float4*>(wr + c0 + 4);
    const float* ai = sa + h * 128 + d0;
    const float* aj = sa + h * 128 + 64 + d0;
    float si = wa.x * ai[0] + wa.y * ai[1] + wa.z * ai[2] + wa.w * ai[3]
             + wb.x * ai[4] + wb.y * ai[5] + wb.z * ai[6] + wb.w * ai[7];
    float sj = wa.x * aj[0] + wa.y * aj[1] + wa.z * aj[2] + wa.w * aj[3]
             + wb.x * aj[4] + wb.y * aj[5] + wb.z * aj[6] + wb.w * aj[7];
#pragma unroll
    for (int o = 1; o < 8; o <<= 1) {
        si += __shfl_xor_sync(0xffffffffu, si, o);
        sj += __shfl_xor_sync(0xffffffffu, sj, o);
    }
    if ((lane & 7) == 0) {
        g_ei[row * Hh + h] = si;
        g_ej[row * Hh + h] = sj;
    }
}

// ---------------- Kernel C: sparse masked softmax + aggregation ----------------
// One block per (b, n). Deterministic compaction of the adjacency row (sorted by j),
// LeakyReLU + softmax over the ~52-entry neighbor list, then gathered weighted sum.
__global__ __launch_bounds__(256) void attn_kernel(const float* __restrict__ adj,
                                                   float* __restrict__ out) {
    __shared__ int   s_idx[Nn];
    __shared__ __align__(16) float s_e[Nn * Hh];
    __shared__ int   s_wcnt[8];
    __shared__ float s_red[8 * Hh];
    __shared__ float s_ei[Hh];

    const int t    = threadIdx.x;
    const int bid  = blockIdx.x;        // = b*1024 + n
    const int b    = bid >> 10;
    const int n    = bid & (Nn - 1);
    const int lane = t & 31;
    const int w    = t >> 5;

    if (t < Hh) s_ei[t] = g_ei[bid * Hh + t];

    // --- Phase 1: compact neighbor list (adj[b,n,j]!=0 || j==n), sorted, no atomics ---
    const float4 av = reinterpret_cast<const float4*>(adj + (size_t)bid * Nn)[t];
    const int j0 = 4 * t;
    const int p0 = (av.x != 0.f) | (j0 == n);
    const int p1 = (av.y != 0.f) | (j0 + 1 == n);
    const int p2 = (av.z != 0.f) | (j0 + 2 == n);
    const int p3 = (av.w != 0.f) | (j0 + 3 == n);
    const int cnt = p0 + p1 + p2 + p3;
    int incl = cnt;
#pragma unroll
    for (int o = 1; o < 32; o <<= 1) {
        int v = __shfl_up_sync(0xffffffffu, incl, o);
        if (lane >= o) incl += v;
    }
    if (lane == 31) s_wcnt[w] = incl;
    __syncthreads();
    int base = 0, total = 0;
#pragma unroll
    for (int ww = 0; ww < 8; ++ww) {
        const int c = s_wcnt[ww];
        total += c;
        if (ww < w) base += c;
    }
    int off = base + incl - cnt;
    if (p0) s_idx[off++] = j0;
    if (p1) s_idx[off++] = j0 + 1;
    if (p2) s_idx[off++] = j0 + 2;
    if (p3) s_idx[off++] = j0 + 3;
    __syncthreads();

    // --- Phase 2: e = leaky_relu(ei + ej) for listed entries; per-head max ---
    const float ei0 = s_ei[0], ei1 = s_ei[1], ei2 = s_ei[2], ei3 = s_ei[3];
    float m0 = -1e30f, m1 = -1e30f, m2 = -1e30f, m3 = -1e30f;
    for (int k = t; k < total; k += 256) {
        const int j = s_idx[k];
        float4 ej = *reinterpret_cast<const float4*>(g_ej + ((size_t)(b << 10) + j) * Hh);
        float e0 = ei0 + ej.x; e0 = e0 > 0.f ? e0 : 0.2f * e0;
        float e1 = ei1 + ej.y; e1 = e1 > 0.f ? e1 : 0.2f * e1;
        float e2 = ei2 + ej.z; e2 = e2 > 0.f ? e2 : 0.2f * e2;
        float e3 = ei3 + ej.w; e3 = e3 > 0.f ? e3 : 0.2f * e3;
        reinterpret_cast<float4*>(s_e)[k] = make_float4(e0, e1, e2, e3);
        m0 = fmaxf(m0, e0); m1 = fmaxf(m1, e1);
        m2 = fmaxf(m2, e2); m3 = fmaxf(m3, e3);
    }
#pragma unroll
    for (int o = 16; o >= 1; o >>= 1) {
        m0 = fmaxf(m0, __shfl_xor_sync(0xffffffffu, m0, o));
        m1 = fmaxf(m1, __shfl_xor_sync(0xffffffffu, m1, o));
        m2 = fmaxf(m2, __shfl_xor_sync(0xffffffffu, m2, o));
        m3 = fmaxf(m3, __shfl_xor_sync(0xffffffffu, m3, o));
    }
    if (lane == 0) { s_red[w*4+0]=m0; s_red[w*4+1]=m1; s_red[w*4+2]=m2; s_red[w*4+3]=m3; }
    __syncthreads();
    float gm0 = -1e30f, gm1 = -1e30f, gm2 = -1e30f, gm3 = -1e30f;
#pragma unroll
    for (int ww = 0; ww < 8; ww++) {
        gm0 = fmaxf(gm0, s_red[ww*4+0]); gm1 = fmaxf(gm1, s_red[ww*4+1]);
        gm2 = fmaxf(gm2, s_red[ww*4+2]); gm3 = fmaxf(gm3, s_red[ww*4+3]);
    }
    __syncthreads();  // all gmax reads done before s_red reuse

    // --- Phase 3: exp + per-head sum ---
    float s0 = 0.f, s1 = 0.f, s2 = 0.f, s3 = 0.f;
    for (int k = t; k < total; k += 256) {
        float4 e = reinterpret_cast<float4*>(s_e)[k];
        e.x = __expf(e.x - gm0); e.y = __expf(e.y - gm1);
        e.z = __expf(e.z - gm2); e.w = __expf(e.w - gm3);
        reinterpret_cast<float4*>(s_e)[k] = e;
        s0 += e.x; s1 += e.y; s2 += e.z; s3 += e.w;
    }
#pragma unroll
    for (int o = 16; o >= 1; o >>= 1) {
        s0 += __shfl_xor_sync(0xffffffffu, s0, o);
        s1 += __shfl_xor_sync(0xffffffffu, s1, o);
        s2 += __shfl_xor_sync(0xffffffffu, s2, o);
        s3 += __shfl_xor_sync(0xffffffffu, s3, o);
    }
    if (lane == 0) { s_red[w*4+0]=s0; s_red[w*4+1]=s1; s_red[w*4+2]=s2; s_red[w*4+3]=s3; }
    __syncthreads();

    // --- Phase 4: out[h,d] = (1/sum_h) * sum_k ex[k,h] * Wx[b, j_k, h*64+d] ---
    const int h = t >> 6;
    const int d = t & 63;
    float gsum = 0.f;
#pragma unroll
    for (int ww = 0; ww < 8; ww++) gsum += s_red[ww*4+h];

    const float* wxb = g_Wx + (size_t)(b << 10) * HD + h * Dd + d;
    float a0 = 0.f, a1 = 0.f, a2 = 0.f, a3 = 0.f;
    int k = 0;
    for (; k + 4 <= total; k += 4) {
        const int i0 = s_idx[k], i1 = s_idx[k+1], i2 = s_idx[k+2], i3 = s_idx[k+3];
        const float w0 = s_e[(k+0)*4 + h], w1 = s_e[(k+1)*4 + h];
        const float w2 = s_e[(k+2)*4 + h], w3 = s_e[(k+3)*4 + h];
        a0 += w0 * __ldg(wxb + (size_t)i0 * HD);
        a1 += w1 * __ldg(wxb + (size_t)i1 * HD);
        a2 += w2 * __ldg(wxb + (size_t)i2 * HD);
        a3 += w3 * __ldg(wxb + (size_t)i3 * HD);
    }
    for (; k < total; ++k)
        a0 += s_e[k*4 + h] * __ldg(wxb + (size_t)s_idx[k] * HD);

    const float acc = (a0 + a1) + (a2 + a3);
    out[(size_t)bid * HD + t] = acc / gsum;
}

// ---------------- launch ----------------
extern "C" void kernel_launch(void* const* d_in, const int* in_sizes, int n_in,
                              void* d_out, int out_size) {
    const float* x   = (const float*)d_in[0];  // (8,1024,256)
    const float* adj = (const float*)d_in[1];  // (8,1024,1024)
    const float* W   = (const float*)d_in[2];  // (256,256)
    const float* a   = (const float*)d_in[3];  // (1,4,128)
    float* out = (float*)d_out;                // (8,1024,256)

    (void)in_sizes; (void)n_in; (void)out_size;

    gemm_kernel<<<dim3(Mrows / BM, HD / BN), 256>>>(x, W);
    eij_kernel<<<Mrows / 8, 256>>>(a);
    attn_kernel<<<Mrows, 256>>>(adj, out);
}